// round 9
// baseline (speedup 1.0000x reference)
#include <cuda_runtime.h>
#include <cstdint>

// Cost-volume correlation, MAX_DISP=4 (81 disps), kernel_size=1.
// out[b, dy*9+dx, y, x] = (1/C) * sum_c in1[b,c,y,x] * in2[b,c,y+dy-4,x+dx-4]
//
// R9: one dy per block (grid.x=9), 4 pixels per thread, full-width 128-px row
// tile. Window = 12 floats via 3x ld.shared.v2.u64 (pairs arrive pre-packed for
// fma.rn.f32x2). 36 acc regs -> 3 CTAs/SM (24 warps). 4-stage cp.async ring.

typedef unsigned long long u64;

__device__ __forceinline__ void fma2(u64 &d, u64 a, u64 b) {
    asm("fma.rn.f32x2 %0, %1, %2, %0;" : "+l"(d) : "l"(a), "l"(b));
}
__device__ __forceinline__ u64 pk(float lo, float hi) {
    u64 r; asm("mov.b64 %0, {%1,%2};" : "=l"(r) : "f"(lo), "f"(hi)); return r;
}
__device__ __forceinline__ void upk(u64 v, float &lo, float &hi) {
    asm("mov.b64 {%0,%1}, %2;" : "=f"(lo), "=f"(hi) : "l"(v));
}

#define CC 128
#define HH 128
#define WW 128
#define HW (HH * WW)
#define NDISP 81
#define TILE_R 8                   // 8 y-rows (one dy -> window row = y+dy-4)
#define TILE_C 136                 // 128 px + 8 halo
#define TILE_N (TILE_R * TILE_C)   // 1088 floats = 4352 B
#define NQUAD (TILE_N / 4)         // 272 16-byte quads
#define STAGES 4
#define STAGE_B (TILE_N * 4)

__global__ __launch_bounds__(256, 3)
void corr_kernel(const float* __restrict__ in1,
                 const float* __restrict__ in2,
                 float* __restrict__ out)
{
    __shared__ __align__(16) float sm[STAGES][TILE_N];

    const int tx  = threadIdx.x;             // 0..31
    const int ty  = threadIdx.y;             // 0..7
    const int tid = ty * 32 + tx;
    const int dy  = blockIdx.x;              // 0..8
    const int y0  = blockIdx.y * 8;
    const int b   = blockIdx.z;

    const int y = y0 + ty;
    const int x = tx * 4;                    // pixels x..x+3 (full-width tile)

    const float* i1 = in1 + ((b * CC) * HH + y) * WW + x;

    // ---- cp.async staging: quad q -> row q/34, col4 (q%34)*4; gx = col4-4 ----
    // gx is 0 mod 4, so quads are entirely in or entirely out of bounds in x.
    const uint32_t sb = (uint32_t)__cvta_generic_to_shared(&sm[0][0]);
    const float* i2b = in2 + (b * CC) * HW;

    const int q0 = tid;
    int r0c = q0 / 34, c0c = (q0 - r0c * 34) * 4;
    int gy0 = y0 - 4 + dy + r0c, gx0 = c0c - 4;
    const bool ok0 = (gy0 >= 0) && (gy0 < HH) && (gx0 >= 0) && (gx0 < WW);
    const float* src0 = i2b + gy0 * WW + gx0;
    const uint32_t dst0 = sb + q0 * 16;

    const int q1 = 256 + tid;                // only tid < 16
    int r1c = q1 / 34, c1c = (q1 - r1c * 34) * 4;
    int gy1 = y0 - 4 + dy + r1c, gx1 = c1c - 4;
    const bool has1 = (tid < NQUAD - 256);
    const bool ok1 = has1 && (gy1 >= 0) && (gy1 < HH) && (gx1 >= 0) && (gx1 < WW);
    const float* src1 = i2b + gy1 * WW + gx1;
    const uint32_t dst1 = sb + q1 * 16;

    // zero never-copied (OOB) slots once, in all stages
    {
        float4 z = make_float4(0.f, 0.f, 0.f, 0.f);
#pragma unroll
        for (int s = 0; s < STAGES; s++) {
            if (!ok0)          *(float4*)&sm[s][q0 * 4] = z;
            if (has1 && !ok1)  *(float4*)&sm[s][q1 * 4] = z;
        }
    }

    // Prologue: issue channels 0..2 into stages 0..2.
#pragma unroll
    for (int c = 0; c < 3; c++) {
        if (ok0) {
            uint32_t d = dst0 + c * STAGE_B;
            asm volatile("cp.async.cg.shared.global [%0], [%1], 16;" :: "r"(d), "l"(src0 + c * HW));
        }
        if (ok1) {
            uint32_t d = dst1 + c * STAGE_B;
            asm volatile("cp.async.cg.shared.global [%0], [%1], 16;" :: "r"(d), "l"(src1 + c * HW));
        }
        asm volatile("cp.async.commit_group;");
    }
    float4 aq0 = *(const float4*)i1;
    float4 aq1 = *(const float4*)(i1 + HW);

    u64   accE[10];                          // even dx: [k]=pair(x,x+1), [5+k]=pair(x+2,x+3)
    float accO[16];                          // odd dx 2t+1: [t*4 + p] = pixel x+p
#pragma unroll
    for (int i = 0; i < 10; i++) accE[i] = 0ull;
#pragma unroll
    for (int i = 0; i < 16; i++) accO[i] = 0.f;

    for (int c = 0; c < CC; c++) {
        asm volatile("cp.async.wait_group 2;" ::: "memory");
        __syncthreads();   // stage c%4 visible; stage (c+3)%4 free (read at c-1)

        float4 an = make_float4(0.f, 0.f, 0.f, 0.f);
        if (c + 2 < CC) an = *(const float4*)(i1 + (c + 2) * HW);
        if (c + 3 < CC) {
            uint32_t sofs = ((c + 3) & 3) * STAGE_B;
            if (ok0)
                asm volatile("cp.async.cg.shared.global [%0], [%1], 16;" :: "r"(dst0 + sofs), "l"(src0 + (c + 3) * HW));
            if (ok1)
                asm volatile("cp.async.cg.shared.global [%0], [%1], 16;" :: "r"(dst1 + sofs), "l"(src1 + (c + 3) * HW));
        }
        asm volatile("cp.async.commit_group;");

        const u64 A01 = pk(aq0.x, aq0.y);
        const u64 A23 = pk(aq0.z, aq0.w);

        // window w[0..11] covers gx = x-4 .. x+7; Pk = (w[2k], w[2k+1]) packed
        const ulonglong2* W = (const ulonglong2*)&sm[c & 3][ty * TILE_C + tx * 4];
        ulonglong2 Q0 = W[0];
        ulonglong2 Q1 = W[1];
        ulonglong2 Q2 = W[2];
        const u64 P0 = Q0.x, P1 = Q0.y, P2 = Q1.x, P3 = Q1.y, P4 = Q2.x, P5 = Q2.y;

        // even dx = 2k: pair0 <- Pk, pair1 <- P{k+1}
        fma2(accE[0], A01, P0);  fma2(accE[5], A23, P1);
        fma2(accE[1], A01, P1);  fma2(accE[6], A23, P2);
        fma2(accE[2], A01, P2);  fma2(accE[7], A23, P3);
        fma2(accE[3], A01, P3);  fma2(accE[8], A23, P4);
        fma2(accE[4], A01, P4);  fma2(accE[9], A23, P5);

        // odd dx = 2t+1: pixels use half-registers of Pt..P{t+2}
        float l0, h0, l1, h1, l2, h2, l3, h3, l4, h4, l5, h5;
        upk(P0, l0, h0); upk(P1, l1, h1); upk(P2, l2, h2);
        upk(P3, l3, h3); upk(P4, l4, h4); upk(P5, l5, h5);
        const float a0 = aq0.x, a1 = aq0.y, a2 = aq0.z, a3 = aq0.w;
        accO[0]  = fmaf(a0, h0, accO[0]);   // t=0
        accO[1]  = fmaf(a1, l1, accO[1]);
        accO[2]  = fmaf(a2, h1, accO[2]);
        accO[3]  = fmaf(a3, l2, accO[3]);
        accO[4]  = fmaf(a0, h1, accO[4]);   // t=1
        accO[5]  = fmaf(a1, l2, accO[5]);
        accO[6]  = fmaf(a2, h2, accO[6]);
        accO[7]  = fmaf(a3, l3, accO[7]);
        accO[8]  = fmaf(a0, h2, accO[8]);   // t=2
        accO[9]  = fmaf(a1, l3, accO[9]);
        accO[10] = fmaf(a2, h3, accO[10]);
        accO[11] = fmaf(a3, l4, accO[11]);
        accO[12] = fmaf(a0, h3, accO[12]);  // t=3
        accO[13] = fmaf(a1, l4, accO[13]);
        accO[14] = fmaf(a2, h4, accO[14]);
        accO[15] = fmaf(a3, l5, accO[15]);

        aq0 = aq1;
        aq1 = an;
    }

    // ---- epilogue: mean over C, float4 stores ----
    const float s = 1.0f / (float)CC;
    float* ob = out + ((b * NDISP + dy * 9) * HH + y) * WW + x;
#pragma unroll
    for (int k = 0; k < 5; k++) {            // even dx = 2k
        float e0, e1, e2, e3;
        upk(accE[k],     e0, e1);
        upk(accE[5 + k], e2, e3);
        float4 o = make_float4(e0 * s, e1 * s, e2 * s, e3 * s);
        *(float4*)(ob + (2 * k) * HW) = o;
    }
#pragma unroll
    for (int t = 0; t < 4; t++) {            // odd dx = 2t+1
        float4 o = make_float4(accO[t * 4 + 0] * s, accO[t * 4 + 1] * s,
                               accO[t * 4 + 2] * s, accO[t * 4 + 3] * s);
        *(float4*)(ob + (2 * t + 1) * HW) = o;
    }
}

extern "C" void kernel_launch(void* const* d_in, const int* in_sizes, int n_in,
                              void* d_out, int out_size)
{
    const float* in1 = (const float*)d_in[0];
    const float* in2 = (const float*)d_in[1];
    float* out = (float*)d_out;

    const int B = in_sizes[0] / (CC * HH * WW);   // 8

    dim3 block(32, 8);
    dim3 grid(9, HH / 8, B);                 // dy fastest -> L2 reuse across dy
    corr_kernel<<<grid, block>>>(in1, in2, out);
}

// round 11
// speedup vs baseline: 1.1997x; 1.1997x over previous
#include <cuda_runtime.h>
#include <cstdint>

// Cost-volume correlation, MAX_DISP=4 (81 disps), kernel_size=1.
// out[b, dy*9+dx, y, x] = (1/C) * sum_c in1[b,c,y,x] * in2[b,c,y+dy-4,x+dx-4]
//
// R11 (= R10 resubmit; prior round died to container infra, no kernel signal):
// per-warp private pipelines. One dy per block; thread (tx,ty) reads only smem
// row ty, and warp ty stages that row itself (lanes 0..16, 2 quads each). So
// the per-channel block barrier becomes __syncwarp. All per-channel addressing
// is strength-reduced to pointer increments.

typedef unsigned long long u64;

__device__ __forceinline__ void fma2(u64 &d, u64 a, u64 b) {
    asm("fma.rn.f32x2 %0, %1, %2, %0;" : "+l"(d) : "l"(a), "l"(b));
}
__device__ __forceinline__ u64 pk(float lo, float hi) {
    u64 r; asm("mov.b64 %0, {%1,%2};" : "=l"(r) : "f"(lo), "f"(hi)); return r;
}
__device__ __forceinline__ void upk(u64 v, float &lo, float &hi) {
    asm("mov.b64 {%0,%1}, %2;" : "=f"(lo), "=f"(hi) : "l"(v));
}
__device__ __forceinline__ void cpasync16(uint32_t d, const float* s) {
    asm volatile("cp.async.cg.shared.global [%0], [%1], 16;" :: "r"(d), "l"(s));
}

#define CC 128
#define HH 128
#define WW 128
#define HW (HH * WW)
#define NDISP 81
#define TILE_C 136                   // 128 px + 8 halo (floats per row)
#define ROW_F TILE_C                 // floats per warp-row
#define ROW_B (TILE_C * 4)           // 544 bytes
#define STAGE_F (8 * TILE_C)         // floats per stage (8 warp-rows)
#define STAGE_B (STAGE_F * 4)        // 4352 bytes
#define STAGES 4

__global__ __launch_bounds__(256, 3)
void corr_kernel(const float* __restrict__ in1,
                 const float* __restrict__ in2,
                 float* __restrict__ out)
{
    __shared__ __align__(16) float sm[STAGES * STAGE_F];

    const int tx = threadIdx.x;              // 0..31
    const int ty = threadIdx.y;              // 0..7  (= warp id = y row = smem row)
    const int dy = blockIdx.x;               // 0..8
    const int y0 = blockIdx.y * 8;
    const int b  = blockIdx.z;

    const int y = y0 + ty;
    const int x = tx * 4;                    // pixels x..x+3

    const float* i1 = in1 + ((b * CC) * HH + y) * WW + x;

    // ---- per-warp staging: warp ty loads row gy = y0+ty+dy-4 (34 quads) ----
    const int gy = y0 + ty + dy - 4;
    const bool rowok = (gy >= 0) && (gy < HH);

    const uint32_t rowsb = (uint32_t)__cvta_generic_to_shared(sm) + ty * ROW_B;
    const int q0 = 2 * tx;                   // lanes 0..16 carry quads 0..33
    const int q1 = 2 * tx + 1;
    const bool ldr = (tx < 17);
    const bool ok0 = ldr && rowok && (q0 >= 1);   // q0<=32 automatic
    const bool ok1 = ldr && rowok && (q1 <= 32);  // q1>=1 automatic
    const float* i2r = in2 + (b * CC) * HW + gy * WW;
    const float* s0 = i2r + (4 * q0 - 4);    // quad q covers gx = 4q-4 .. 4q-1
    const float* s1 = i2r + (4 * q1 - 4);
    const uint32_t d0 = rowsb + q0 * 16;
    const uint32_t d1 = rowsb + q1 * 16;

    // zero never-written (OOB) slots once, all stages (own row only)
    if (ldr) {
        float4 z = make_float4(0.f, 0.f, 0.f, 0.f);
        float* rowg = sm + ty * ROW_F;
#pragma unroll
        for (int s = 0; s < STAGES; s++) {
            if (!ok0) *(float4*)(rowg + s * STAGE_F + q0 * 4) = z;
            if (!ok1) *(float4*)(rowg + s * STAGE_F + q1 * 4) = z;
        }
    }

    // Prologue: channels 0..2 into stages 0..2 (one commit group each).
#pragma unroll
    for (int c = 0; c < 3; c++) {
        if (ok0) cpasync16(d0 + c * STAGE_B, s0 + c * HW);
        if (ok1) cpasync16(d1 + c * STAGE_B, s1 + c * HW);
        asm volatile("cp.async.commit_group;");
    }
    float4 aq0 = *(const float4*)i1;
    float4 aq1 = *(const float4*)(i1 + HW);

    // strength-reduced pointers
    const float* i1n = i1 + 2 * HW;          // in1 channel c+2
    const float* s0n = s0 + 3 * HW;          // in2 channel c+3
    const float* s1n = s1 + 3 * HW;
    uint32_t so = 3 * STAGE_B;               // issue-stage byte offset (rotating)
    const float* smrow = sm + ty * ROW_F + tx * 4;   // compute base, stage 0
    int cb = 0;                              // compute-stage float offset

    u64   accE[10];                          // even dx: [k]=(x,x+1), [5+k]=(x+2,x+3)
    float accO[16];                          // odd dx 2t+1: [t*4+p] = pixel x+p
#pragma unroll
    for (int i = 0; i < 10; i++) accE[i] = 0ull;
#pragma unroll
    for (int i = 0; i < 16; i++) accO[i] = 0.f;

    for (int c = 0; c < CC; c++) {
        asm volatile("cp.async.wait_group 2;" ::: "memory");
        __syncwarp();   // own-warp lanes: loads visible; last iter's reads done

        float4 an = make_float4(0.f, 0.f, 0.f, 0.f);
        if (c + 2 < CC) { an = *(const float4*)i1n; i1n += HW; }
        if (c + 3 < CC) {
            if (ok0) cpasync16(d0 + so, s0n);
            if (ok1) cpasync16(d1 + so, s1n);
            s0n += HW; s1n += HW;
        }
        asm volatile("cp.async.commit_group;");
        so += STAGE_B; if (so == STAGES * STAGE_B) so = 0;

        const u64 A01 = pk(aq0.x, aq0.y);
        const u64 A23 = pk(aq0.z, aq0.w);

        // window w[0..11] = gx x-4..x+7 ; Pk = packed (w[2k], w[2k+1])
        const ulonglong2* W = (const ulonglong2*)(smrow + cb);
        ulonglong2 Q0 = W[0];
        ulonglong2 Q1 = W[1];
        ulonglong2 Q2 = W[2];
        cb += STAGE_F; if (cb == STAGES * STAGE_F) cb = 0;
        const u64 P0 = Q0.x, P1 = Q0.y, P2 = Q1.x, P3 = Q1.y, P4 = Q2.x, P5 = Q2.y;

        // even dx = 2k
        fma2(accE[0], A01, P0);  fma2(accE[5], A23, P1);
        fma2(accE[1], A01, P1);  fma2(accE[6], A23, P2);
        fma2(accE[2], A01, P2);  fma2(accE[7], A23, P3);
        fma2(accE[3], A01, P3);  fma2(accE[8], A23, P4);
        fma2(accE[4], A01, P4);  fma2(accE[9], A23, P5);

        // odd dx = 2t+1 via register halves
        float l0, h0, l1, h1, l2, h2, l3, h3, l4, h4, l5, h5;
        upk(P0, l0, h0); upk(P1, l1, h1); upk(P2, l2, h2);
        upk(P3, l3, h3); upk(P4, l4, h4); upk(P5, l5, h5);
        const float a0 = aq0.x, a1 = aq0.y, a2 = aq0.z, a3 = aq0.w;
        accO[0]  = fmaf(a0, h0, accO[0]);
        accO[1]  = fmaf(a1, l1, accO[1]);
        accO[2]  = fmaf(a2, h1, accO[2]);
        accO[3]  = fmaf(a3, l2, accO[3]);
        accO[4]  = fmaf(a0, h1, accO[4]);
        accO[5]  = fmaf(a1, l2, accO[5]);
        accO[6]  = fmaf(a2, h2, accO[6]);
        accO[7]  = fmaf(a3, l3, accO[7]);
        accO[8]  = fmaf(a0, h2, accO[8]);
        accO[9]  = fmaf(a1, l3, accO[9]);
        accO[10] = fmaf(a2, h3, accO[10]);
        accO[11] = fmaf(a3, l4, accO[11]);
        accO[12] = fmaf(a0, h3, accO[12]);
        accO[13] = fmaf(a1, l4, accO[13]);
        accO[14] = fmaf(a2, h4, accO[14]);
        accO[15] = fmaf(a3, l5, accO[15]);

        aq0 = aq1;
        aq1 = an;
    }

    // ---- epilogue: mean over C, float4 stores ----
    const float s = 1.0f / (float)CC;
    float* ob = out + ((b * NDISP + dy * 9) * HH + y) * WW + x;
#pragma unroll
    for (int k = 0; k < 5; k++) {            // even dx = 2k
        float e0, e1, e2, e3;
        upk(accE[k],     e0, e1);
        upk(accE[5 + k], e2, e3);
        *(float4*)(ob + (2 * k) * HW) =
            make_float4(e0 * s, e1 * s, e2 * s, e3 * s);
    }
#pragma unroll
    for (int t = 0; t < 4; t++) {            // odd dx = 2t+1
        *(float4*)(ob + (2 * t + 1) * HW) =
            make_float4(accO[t * 4 + 0] * s, accO[t * 4 + 1] * s,
                        accO[t * 4 + 2] * s, accO[t * 4 + 3] * s);
    }
}

extern "C" void kernel_launch(void* const* d_in, const int* in_sizes, int n_in,
                              void* d_out, int out_size)
{
    const float* in1 = (const float*)d_in[0];
    const float* in2 = (const float*)d_in[1];
    float* out = (float*)d_out;

    const int B = in_sizes[0] / (CC * HH * WW);   // 8

    dim3 block(32, 8);
    dim3 grid(9, HH / 8, B);
    corr_kernel<<<grid, block>>>(in1, in2, out);
}